// round 2
// baseline (speedup 1.0000x reference)
#include <cuda_runtime.h>
#include <stdint.h>

// BinarizedLinear: act[d,o] = sum_i W[d,o,i] * x[d,i];  out[d,o] = (act > bias[d,o]) ? 1.0 : 0.0
// D=64, OUT=2048, IN=2048. All buffers float32 (harness materializes jax bools as f32).
// Pure HBM-stream kernel: 1.074 GB of weights read once. One warp per output row.

#define D_DIRS 64
#define OUT_F  2048
#define IN_F   2048
#define ROWS_PER_BLOCK 8            // 8 warps per block, one row each
#define THREADS (ROWS_PER_BLOCK * 32)

__global__ __launch_bounds__(THREADS)
void binlin_kernel(const float* __restrict__ W,
                   const float* __restrict__ x,
                   const float* __restrict__ bias,
                   float* __restrict__ out)
{
    __shared__ float xf[IN_F];

    // 2048 rows per direction / 8 rows per block = 256 blocks per direction (exact).
    const int d     = blockIdx.x >> 8;          // blockIdx.x / 256
    const int obase = (blockIdx.x & 255) * ROWS_PER_BLOCK;

    // Stage x[d,:] (already 0.0/1.0 floats) in smem, vectorized 16B copies.
    const float4* xr4 = (const float4*)(x + (size_t)d * IN_F);
    float4*       xs4 = (float4*)xf;
    #pragma unroll
    for (int i = threadIdx.x; i < IN_F / 4; i += THREADS)
        xs4[i] = xr4[i];
    __syncthreads();

    const int warp = threadIdx.x >> 5;
    const int lane = threadIdx.x & 31;
    const int o    = obase + warp;

    // Warp streams one 8 KB weight row: 16 x float4 per lane, fully unrolled
    // (high MLP_p1 -> DRAM latency hidden behind outstanding LDG.128s).
    const float4* __restrict__ wr =
        (const float4*)(W + ((size_t)d * OUT_F + o) * IN_F);

    float acc = 0.0f;
    #pragma unroll
    for (int it = 0; it < 16; ++it) {
        float4 w  = __ldg(&wr[it * 32 + lane]);
        float4 xv = *(const float4*)(&xf[it * 128 + lane * 4]);
        acc = fmaf(w.x, xv.x, acc);
        acc = fmaf(w.y, xv.y, acc);
        acc = fmaf(w.z, xv.z, acc);
        acc = fmaf(w.w, xv.w, acc);
    }

    // Butterfly warp reduction.
    #pragma unroll
    for (int s = 16; s > 0; s >>= 1)
        acc += __shfl_xor_sync(0xFFFFFFFFu, acc, s);

    if (lane == 0) {
        const int idx = d * OUT_F + o;
        out[idx] = (acc > bias[idx]) ? 1.0f : 0.0f;
    }
}

extern "C" void kernel_launch(void* const* d_in, const int* in_sizes, int n_in,
                              void* d_out, int out_size)
{
    // metadata order: weight_noise (f32, D*OUT*IN), x (f32 0/1, D*IN),
    //                 bias_noise (f32, D*OUT). output: f32 0/1 (D*OUT).
    const float* W    = (const float*)d_in[0];
    const float* x    = (const float*)d_in[1];
    const float* bias = (const float*)d_in[2];
    float*       out  = (float*)d_out;

    const int total_rows = D_DIRS * OUT_F;                  // 131072
    const int grid       = total_rows / ROWS_PER_BLOCK;     // 16384
    binlin_kernel<<<grid, THREADS>>>(W, x, bias, out);
}